// round 16
// baseline (speedup 1.0000x reference)
#include <cuda_runtime.h>
#include <cuda_fp16.h>
#include <math.h>
#include <stdint.h>

#define V_ 32000
#define E_ 1024
#define U_ 1024
#define B_ 64
#define S_ 1024

#define BM 64
#define BN 64
#define BK 32
#define NKT (E_ / BK)            // 32 k-tiles
#define SROW 40                  // padded row stride (fp16 elems) = 80 bytes
#define A_TILE (BM * SROW * 2)   // 5120 B
#define B_TILE (BN * SROW * 2)   // 5120 B
#define STAGE_BYTES (A_TILE + 3 * B_TILE)   // 20480 B
#define STAGES 4
#define SMEM_DYN (STAGES * STAGE_BYTES)     // 81920 B -> 2 CTAs/SM

#define NCH 16                   // scan chunks
#define CHL (S_ / NCH)           // 64 timesteps per chunk

// ---------------- device scratch (__device__ globals; no allocs allowed) ----
__device__ int     g_cnt;
__device__ int     g_remap[V_];
__device__ int     g_ulist[V_];
__device__ int     g_sent[B_ * S_];
__device__ __half2 g_tab[(size_t)V_ * U_];   // (f_n, i_n*h~) packed, row = compact id
__device__ float   g_P [NCH * B_ * U_];
__device__ float   g_Q [NCH * B_ * U_];
__device__ __half  g_embc[(size_t)V_ * E_]; // compacted fp16 embedding rows
__device__ __half  g_wt[3][(size_t)U_ * E_];

// ---------------- asm helpers (base sm_103 ISA only) ------------------------
__device__ __forceinline__ uint32_t smem_u32(const void* p) {
    uint32_t a;
    asm("{ .reg .u64 t; cvta.to.shared.u64 t, %1; cvt.u32.u64 %0, t; }" : "=r"(a) : "l"(p));
    return a;
}
__device__ __forceinline__ void cp16(uint32_t dst, const void* src) {
    asm volatile("cp.async.cg.shared.global [%0], [%1], 16;" :: "r"(dst), "l"(src));
}
#define CP_COMMIT() asm volatile("cp.async.commit_group;" ::: "memory")
#define CP_WAIT(N)  asm volatile("cp.async.wait_group %0;" :: "n"(N) : "memory")

__device__ __forceinline__ void ldsm4(uint32_t* r, uint32_t addr) {
    asm volatile("ldmatrix.sync.aligned.m8n8.x4.shared.b16 {%0,%1,%2,%3}, [%4];"
        : "=r"(r[0]), "=r"(r[1]), "=r"(r[2]), "=r"(r[3]) : "r"(addr));
}
__device__ __forceinline__ void mma16816(float* c, const uint32_t* a, const uint32_t* b) {
    asm volatile(
        "mma.sync.aligned.m16n8k16.row.col.f32.f16.f16.f32 "
        "{%0,%1,%2,%3}, {%4,%5,%6,%7}, {%8,%9}, {%0,%1,%2,%3};"
        : "+f"(c[0]), "+f"(c[1]), "+f"(c[2]), "+f"(c[3])
        : "r"(a[0]), "r"(a[1]), "r"(a[2]), "r"(a[3]), "r"(b[0]), "r"(b[1]));
}
__device__ __forceinline__ bool sent_is64(const int* __restrict__ s) {
    #pragma unroll 4
    for (int j = 0; j < 64; j++)
        if (__ldg(&s[2 * j + 1]) != 0) return false;
    return true;
}

// ---------------- kernel P0: reset remap + counter ---------------------------
__global__ __launch_bounds__(256) void zero_k() {
    int v = blockIdx.x * 256 + threadIdx.x;
    if (v < V_) g_remap[v] = -1;
    if (v == 0) g_cnt = 0;
}

// ---------------- kernel P1: mark unique tokens, build compact list ---------
__global__ __launch_bounds__(256) void mark_k(const int* __restrict__ sent32) {
    bool is64 = sent_is64(sent32);
    int i = blockIdx.x * 256 + threadIdx.x;            // 0 .. B*S-1
    int tok = is64 ? __ldg(&sent32[2 * i]) : __ldg(&sent32[i]);
    int old = atomicCAS(&g_remap[tok], -1, -2);
    if (old == -1) {
        int pos = atomicAdd(&g_cnt, 1);
        g_ulist[pos] = tok;
        __threadfence();
        g_remap[tok] = pos;
    }
}

// ---------------- kernel P2: rewrite sentence with compact ids --------------
__global__ __launch_bounds__(256) void sentmap_k(const int* __restrict__ sent32) {
    bool is64 = sent_is64(sent32);
    int i = blockIdx.x * 256 + threadIdx.x;
    int tok = is64 ? __ldg(&sent32[2 * i]) : __ldg(&sent32[i]);
    g_sent[i] = g_remap[tok];
}

// ---------------- kernel 0a: gather+convert emb rows (8 rows/block, MLP=8) --
__global__ __launch_bounds__(256) void gather_emb_k(const float* __restrict__ emb) {
    const int cnt = g_cnt;
    const int r0 = blockIdx.x * 8;
    if (r0 >= cnt) return;
    const int t = threadIdx.x;
    int toks[8];
    #pragma unroll
    for (int q = 0; q < 8; q++) {
        int r = r0 + q;
        toks[q] = __ldg(&g_ulist[r < cnt ? r : cnt - 1]);
    }
    float4 x[8];
    #pragma unroll
    for (int q = 0; q < 8; q++)
        x[q] = __ldg((const float4*)(emb + (size_t)toks[q] * E_) + t);
    #pragma unroll
    for (int q = 0; q < 8; q++) {
        int r = r0 + q;
        if (r >= cnt) break;
        __half2* dst = (__half2*)(g_embc + (size_t)r * E_);
        dst[2 * t + 0] = __floats2half2_rn(x[q].x, x[q].y);
        dst[2 * t + 1] = __floats2half2_rn(x[q].z, x[q].w);
    }
}

// ---------------- kernel 0b: transpose W[e,u] -> Wt[u,e] fp16 ---------------
__global__ void transpose_w_k(
    const float* __restrict__ Wf, const float* __restrict__ Wi, const float* __restrict__ Wh) {
    __shared__ float t[32][33];
    int mat = blockIdx.z;
    const float* W = (mat == 0) ? Wf : (mat == 1) ? Wi : Wh;
    int u0 = blockIdx.x * 32, e0 = blockIdx.y * 32;
    int tx = threadIdx.x, ty = threadIdx.y;   // block (32, 8)
    #pragma unroll
    for (int r = 0; r < 32; r += 8)
        t[ty + r][tx] = W[(size_t)(e0 + ty + r) * U_ + u0 + tx];
    __syncthreads();
    __half* oh = g_wt[mat];
    #pragma unroll
    for (int r = 0; r < 32; r += 8)
        oh[(size_t)(u0 + ty + r) * E_ + e0 + tx] = __float2half_rn(t[tx][ty + r]);
}

// ---------------- kernel 1: pipelined fp16 mma triple GEMM + gates ----------
// Round-10 loop order (trailing load_stage — measured best), but 512 threads:
// 16 warps (4x4), warp tile 16x16 -> acc 24 regs/thread, 32 warps/SM
// (8/SMSP), double the latency cover at unchanged smem/CTA count.
__global__ __launch_bounds__(512, 2) void gates_mma(
    const float* __restrict__ bfb, const float* __restrict__ bib,
    const float* __restrict__ bhb)
{
    const int cnt = g_cnt;
    const int m0 = blockIdx.y * BM;
    if (m0 >= cnt) return;
    const int n0 = blockIdx.x * BN;

    extern __shared__ char smem[];
    const uint32_t sb = smem_u32(smem);
    const int tid  = threadIdx.x;
    const int lane = tid & 31, wid = tid >> 5;
    const int wm = wid & 3;          // 4 warps in m  (4*16 = 64)
    const int wn = wid >> 2;         // 4 warps in n  (4*16 = 64)

    float acc[3][2][4];
    #pragma unroll
    for (int m = 0; m < 3; m++)
        #pragma unroll
        for (int j = 0; j < 2; j++)
            #pragma unroll
            for (int r = 0; r < 4; r++) acc[m][j][r] = 0.f;

    // ---- stage loader: 2 cp.async per thread over 1024 16B chunks ----------
    // chunk c: tile = c>>8 (0=A, 1..3=B), row = (c>>2)&63, seg = c&3
    const int c0 = tid, c1 = tid + 512;
    const int t0_ = c0 >> 8, r0_ = (c0 >> 2) & 63, s0_ = c0 & 3;
    const int t1_ = c1 >> 8, r1_ = (c1 >> 2) & 63, s1_ = c1 & 3;
    const int ar0 = (m0 + r0_ < cnt) ? (m0 + r0_) : (cnt - 1);
    const __half* src0 = (t0_ == 0)
        ? g_embc + (size_t)ar0 * E_ + s0_ * 8
        : g_wt[t0_ - 1] + (size_t)(n0 + r0_) * E_ + s0_ * 8;
    const __half* src1 = g_wt[t1_ - 1] + (size_t)(n0 + r1_) * E_ + s1_ * 8;  // c1 >= 512 -> tile 2,3
    const uint32_t dst0 = t0_ * A_TILE + r0_ * (SROW * 2) + s0_ * 16;
    const uint32_t dst1 = t1_ * A_TILE + r1_ * (SROW * 2) + s1_ * 16;
    auto load_stage = [&](int kt, int s) {
        const uint32_t base = sb + s * STAGE_BYTES;
        const int k0 = kt * BK;
        cp16(base + dst0, src0 + k0);
        cp16(base + dst1, src1 + k0);
        CP_COMMIT();
    };

    const int lq = lane >> 3, lr = lane & 7;
    const uint32_t a_ld = (wm * 16 + (lq & 1) * 8 + lr) * (SROW * 2) + (lq >> 1) * 16;
    const uint32_t b_ld = A_TILE + (wn * 16 + (lq >> 1) * 8 + lr) * (SROW * 2) + (lq & 1) * 16;

    load_stage(0, 0);
    load_stage(1, 1);
    load_stage(2, 2);

    for (int kt = 0; kt < NKT; ++kt) {
        if      (kt < NKT - 2) { CP_WAIT(2); }
        else if (kt < NKT - 1) { CP_WAIT(1); }
        else                   { CP_WAIT(0); }
        __syncthreads();

        const uint32_t base = sb + (kt & (STAGES - 1)) * STAGE_BYTES;
        #pragma unroll
        for (int ks = 0; ks < 2; ++ks) {
            uint32_t aF[4];
            ldsm4(aF, base + a_ld + ks * 32);
            #pragma unroll
            for (int mat = 0; mat < 3; mat++) {
                uint32_t bF[4];
                ldsm4(bF, base + b_ld + mat * B_TILE + ks * 32);
                #pragma unroll
                for (int j = 0; j < 2; j++)
                    mma16816(acc[mat][j], aF, &bF[j * 2]);
            }
        }
        // trailing load (measured best position): writes stage (kt+3)&3 ==
        // (kt-1)&3 whose readers all completed before this iteration's barrier.
        if (kt + 3 < NKT) load_stage(kt + 3, (kt + 3) & (STAGES - 1));
    }

    // ---- epilogue: gate math (2 EX2 + 1 RCP per element), half2 stores -----
    #pragma unroll
    for (int j = 0; j < 2; j++) {
        int col = n0 + wn * 16 + j * 8 + (lane & 3) * 2;
        float2 bfv = *(const float2*)(bfb + col);
        float2 biv = *(const float2*)(bib + col);
        float2 bhv = *(const float2*)(bhb + col);
        #pragma unroll
        for (int rh = 0; rh < 2; rh++) {
            int row = m0 + wm * 16 + (lane >> 2) + rh * 8;
            if (row >= cnt) continue;
            float ef0 = __expf(-(acc[0][j][rh * 2 + 0] + bfv.x));
            float ef1 = __expf(-(acc[0][j][rh * 2 + 1] + bfv.y));
            float ei0 = __expf(-(acc[1][j][rh * 2 + 0] + biv.x));
            float ei1 = __expf(-(acc[1][j][rh * 2 + 1] + biv.y));
            float zh0 = acc[2][j][rh * 2 + 0] + bhv.x;
            float zh1 = acc[2][j][rh * 2 + 1] + bhv.y;
            float r0 = 1.f / (2.f + ef0 + ei0);
            float r1 = 1.f / (2.f + ef1 + ei1);
            __half2 p0 = __floats2half2_rn((1.f + ei0) * r0, (1.f + ef0) * r0 * zh0);
            __half2 p1 = __floats2half2_rn((1.f + ei1) * r1, (1.f + ef1) * r1 * zh1);
            *(uint2*)&g_tab[(size_t)row * U_ + col] =
                make_uint2(*(uint32_t*)&p0, *(uint32_t*)&p1);
        }
    }
}

// ---------------- kernel 2a: chunked scan, 4 u per thread (uint4 loads) -----
__global__ __launch_bounds__(256) void scan_part()
{
    const int u0 = threadIdx.x * 4;
    const int b = blockIdx.y;
    const int c = blockIdx.z;
    const int4* sr4 = (const int4*)(g_sent + b * S_ + c * CHL);

    float P0 = 1.f, P1 = 1.f, P2 = 1.f, P3 = 1.f;
    float h0 = 0.f, h1 = 0.f, h2 = 0.f, h3 = 0.f;
    #pragma unroll 2
    for (int tq = 0; tq < CHL / 4; tq++) {
        int4 rid4 = __ldg(&sr4[tq]);
        int rids[4] = { rid4.x, rid4.y, rid4.z, rid4.w };
        #pragma unroll
        for (int s = 0; s < 4; s++) {
            uint4 v = __ldg((const uint4*)(g_tab + (size_t)rids[s] * U_ + u0));
            float2 a0 = __half22float2(*(__half2*)&v.x);
            float2 a1 = __half22float2(*(__half2*)&v.y);
            float2 a2 = __half22float2(*(__half2*)&v.z);
            float2 a3 = __half22float2(*(__half2*)&v.w);
            h0 = fmaf(a0.x, h0, a0.y);  P0 *= a0.x;
            h1 = fmaf(a1.x, h1, a1.y);  P1 *= a1.x;
            h2 = fmaf(a2.x, h2, a2.y);  P2 *= a2.x;
            h3 = fmaf(a3.x, h3, a3.y);  P3 *= a3.x;
        }
    }
    size_t idx = ((size_t)c * B_ + b) * U_ + u0;
    *(float4*)&g_P[idx] = make_float4(P0, P1, P2, P3);
    *(float4*)&g_Q[idx] = make_float4(h0, h1, h2, h3);
}

// ---------------- kernel 3: fused combine + head -----------------------------
__global__ __launch_bounds__(256) void head_kernel(
    const float* __restrict__ W1, const float* __restrict__ b1,
    const float* __restrict__ W2, const float* __restrict__ b2,
    float* __restrict__ out)
{
    __shared__ float w12[U_];
    __shared__ float red[256];
    const int b = blockIdx.x, tid = threadIdx.x;

    for (int u = tid; u < U_; u += 256) {
        float s = 0.f;
        #pragma unroll
        for (int c = 0; c < 64; c++) s = fmaf(W1[u * 64 + c], W2[c], s);
        w12[u] = s;
    }

    float p = 0.f;
    #pragma unroll
    for (int q = 0; q < U_ / 256; q++) {
        int u = q * 256 + tid;
        float h = 0.f;
        #pragma unroll
        for (int c = 0; c < NCH; c++) {
            size_t idx = ((size_t)c * B_ + b) * U_ + u;
            h = fmaf(g_P[idx], h, g_Q[idx]);
        }
        p = fmaf(h, w12[u], p);
    }
    __syncthreads();
    red[tid] = p;
    __syncthreads();
    #pragma unroll
    for (int s = 128; s > 0; s >>= 1) {
        if (tid < s) red[tid] += red[tid + s];
        __syncthreads();
    }
    if (tid == 0) {
        float c = 0.f;
        #pragma unroll
        for (int j = 0; j < 64; j++) c = fmaf(b1[j], W2[j], c);
        out[b] = 1.f / (1.f + expf(-(red[0] + c + b2[0])));
    }
}

// ---------------- host -------------------------------------------------------
extern "C" void kernel_launch(void* const* d_in, const int* in_sizes, int n_in,
                              void* d_out, int out_size)
{
    const int*   sent = (const int*)  d_in[0];
    const float* emb  = (const float*)d_in[1];
    const float* Wf   = (const float*)d_in[2];
    const float* bf   = (const float*)d_in[3];
    const float* Wi   = (const float*)d_in[4];
    const float* bi   = (const float*)d_in[5];
    const float* Wh   = (const float*)d_in[6];
    const float* bh   = (const float*)d_in[7];
    const float* W1   = (const float*)d_in[8];
    const float* b1   = (const float*)d_in[9];
    const float* W2   = (const float*)d_in[10];
    const float* b2   = (const float*)d_in[11];
    float* out = (float*)d_out;

    cudaFuncSetAttribute(gates_mma, cudaFuncAttributeMaxDynamicSharedMemorySize, SMEM_DYN);

    zero_k<<<(V_ + 255) / 256, 256>>>();
    mark_k<<<(B_ * S_) / 256, 256>>>(sent);
    sentmap_k<<<(B_ * S_) / 256, 256>>>(sent);
    gather_emb_k<<<(V_ + 7) / 8, 256>>>(emb);
    transpose_w_k<<<dim3(U_ / 32, E_ / 32, 3), dim3(32, 8)>>>(Wf, Wi, Wh);
    gates_mma<<<dim3(U_ / BN, (V_ + BM - 1) / BM), 512, SMEM_DYN>>>(bf, bi, bh);
    scan_part<<<dim3(1, B_, NCH), 256>>>();
    head_kernel<<<B_, 256>>>(W1, b1, W2, b2, out);
}

// round 17
// speedup vs baseline: 1.2243x; 1.2243x over previous
#include <cuda_runtime.h>
#include <cuda_fp16.h>
#include <math.h>
#include <stdint.h>

#define V_ 32000
#define E_ 1024
#define U_ 1024
#define B_ 64
#define S_ 1024

#define BM 64
#define BN 64
#define BK 32
#define NKT (E_ / BK)            // 32 k-tiles
#define SROW 40                  // padded row stride (fp16 elems) = 80 bytes
#define A_TILE (BM * SROW * 2)   // 5120 B
#define B_TILE (BN * SROW * 2)   // 5120 B
#define STAGE_BYTES (A_TILE + 3 * B_TILE)   // 20480 B
#define STAGES 3
#define SMEM_DYN (STAGES * STAGE_BYTES)     // 61440 B -> 3 CTAs/SM

#define NCH 16                   // scan chunks
#define CHL (S_ / NCH)           // 64 timesteps per chunk

// ---------------- device scratch (__device__ globals; no allocs allowed) ----
__device__ int     g_cnt;
__device__ int     g_remap[V_];
__device__ int     g_ulist[V_];
__device__ int     g_sent[B_ * S_];
__device__ __half2 g_tab[(size_t)V_ * U_];   // (f_n, i_n*h~) packed, row = compact id
__device__ float   g_P [NCH * B_ * U_];
__device__ float   g_Q [NCH * B_ * U_];
__device__ __half  g_embc[(size_t)V_ * E_]; // compacted fp16 embedding rows
__device__ __half  g_wt[3][(size_t)U_ * E_];

// ---------------- asm helpers (base sm_103 ISA only) ------------------------
__device__ __forceinline__ uint32_t smem_u32(const void* p) {
    uint32_t a;
    asm("{ .reg .u64 t; cvta.to.shared.u64 t, %1; cvt.u32.u64 %0, t; }" : "=r"(a) : "l"(p));
    return a;
}
__device__ __forceinline__ void cp16(uint32_t dst, const void* src) {
    asm volatile("cp.async.cg.shared.global [%0], [%1], 16;" :: "r"(dst), "l"(src));
}
#define CP_COMMIT() asm volatile("cp.async.commit_group;" ::: "memory")
#define CP_WAIT(N)  asm volatile("cp.async.wait_group %0;" :: "n"(N) : "memory")

__device__ __forceinline__ void ldsm4(uint32_t* r, uint32_t addr) {
    asm volatile("ldmatrix.sync.aligned.m8n8.x4.shared.b16 {%0,%1,%2,%3}, [%4];"
        : "=r"(r[0]), "=r"(r[1]), "=r"(r[2]), "=r"(r[3]) : "r"(addr));
}
__device__ __forceinline__ void mma16816(float* c, const uint32_t* a, const uint32_t* b) {
    asm volatile(
        "mma.sync.aligned.m16n8k16.row.col.f32.f16.f16.f32 "
        "{%0,%1,%2,%3}, {%4,%5,%6,%7}, {%8,%9}, {%0,%1,%2,%3};"
        : "+f"(c[0]), "+f"(c[1]), "+f"(c[2]), "+f"(c[3])
        : "r"(a[0]), "r"(a[1]), "r"(a[2]), "r"(a[3]), "r"(b[0]), "r"(b[1]));
}
__device__ __forceinline__ bool sent_is64(const int* __restrict__ s) {
    #pragma unroll 4
    for (int j = 0; j < 64; j++)
        if (__ldg(&s[2 * j + 1]) != 0) return false;
    return true;
}

// ---------------- kernel P0: reset remap + counter ---------------------------
__global__ __launch_bounds__(256) void zero_k() {
    int v = blockIdx.x * 256 + threadIdx.x;
    if (v < V_) g_remap[v] = -1;
    if (v == 0) g_cnt = 0;
}

// ---------------- kernel P1: mark unique tokens, build compact list ---------
__global__ __launch_bounds__(256) void mark_k(const int* __restrict__ sent32) {
    bool is64 = sent_is64(sent32);
    int i = blockIdx.x * 256 + threadIdx.x;            // 0 .. B*S-1
    int tok = is64 ? __ldg(&sent32[2 * i]) : __ldg(&sent32[i]);
    int old = atomicCAS(&g_remap[tok], -1, -2);
    if (old == -1) {
        int pos = atomicAdd(&g_cnt, 1);
        g_ulist[pos] = tok;
        __threadfence();
        g_remap[tok] = pos;
    }
}

// ---------------- kernel P2: rewrite sentence with compact ids --------------
__global__ __launch_bounds__(256) void sentmap_k(const int* __restrict__ sent32) {
    bool is64 = sent_is64(sent32);
    int i = blockIdx.x * 256 + threadIdx.x;
    int tok = is64 ? __ldg(&sent32[2 * i]) : __ldg(&sent32[i]);
    g_sent[i] = g_remap[tok];
}

// ---------------- kernel 0a: gather+convert emb rows (8 rows/block, MLP=8) --
__global__ __launch_bounds__(256) void gather_emb_k(const float* __restrict__ emb) {
    const int cnt = g_cnt;
    const int r0 = blockIdx.x * 8;
    if (r0 >= cnt) return;
    const int t = threadIdx.x;
    int toks[8];
    #pragma unroll
    for (int q = 0; q < 8; q++) {
        int r = r0 + q;
        toks[q] = __ldg(&g_ulist[r < cnt ? r : cnt - 1]);
    }
    float4 x[8];
    #pragma unroll
    for (int q = 0; q < 8; q++)
        x[q] = __ldg((const float4*)(emb + (size_t)toks[q] * E_) + t);
    #pragma unroll
    for (int q = 0; q < 8; q++) {
        int r = r0 + q;
        if (r >= cnt) break;
        __half2* dst = (__half2*)(g_embc + (size_t)r * E_);
        dst[2 * t + 0] = __floats2half2_rn(x[q].x, x[q].y);
        dst[2 * t + 1] = __floats2half2_rn(x[q].z, x[q].w);
    }
}

// ---------------- kernel 0b: transpose W[e,u] -> Wt[u,e] fp16 ---------------
__global__ void transpose_w_k(
    const float* __restrict__ Wf, const float* __restrict__ Wi, const float* __restrict__ Wh) {
    __shared__ float t[32][33];
    int mat = blockIdx.z;
    const float* W = (mat == 0) ? Wf : (mat == 1) ? Wi : Wh;
    int u0 = blockIdx.x * 32, e0 = blockIdx.y * 32;
    int tx = threadIdx.x, ty = threadIdx.y;   // block (32, 8)
    #pragma unroll
    for (int r = 0; r < 32; r += 8)
        t[ty + r][tx] = W[(size_t)(e0 + ty + r) * U_ + u0 + tx];
    __syncthreads();
    __half* oh = g_wt[mat];
    #pragma unroll
    for (int r = 0; r < 32; r += 8)
        oh[(size_t)(u0 + ty + r) * E_ + e0 + tx] = __float2half_rn(t[tx][ty + r]);
}

// ---------------- kernel 1: pipelined fp16 mma triple GEMM + gates ----------
// Round-10 loop/shape EXACTLY (8 warps, warp tile 32x16, per-ks inner loop,
// trailing load_stage). Two deltas only: STAGES=3 and launch_bounds(256,3)
// -> 3 CTAs/SM (24 warps, 6/SMSP) at the same MMA:ldsm ratio.
__global__ __launch_bounds__(256, 3) void gates_mma(
    const float* __restrict__ bfb, const float* __restrict__ bib,
    const float* __restrict__ bhb)
{
    const int cnt = g_cnt;
    const int m0 = blockIdx.y * BM;
    if (m0 >= cnt) return;
    const int n0 = blockIdx.x * BN;

    extern __shared__ char smem[];
    const uint32_t sb = smem_u32(smem);
    const int tid  = threadIdx.x;
    const int lane = tid & 31, wid = tid >> 5;
    const int wm = wid & 1;          // 2 warps in m  (2*32 = 64)
    const int wn = wid >> 1;         // 4 warps in n  (4*16 = 64)

    float acc[3][2][2][4];
    #pragma unroll
    for (int m = 0; m < 3; m++)
        #pragma unroll
        for (int t = 0; t < 2; t++)
            #pragma unroll
            for (int j = 0; j < 2; j++)
                #pragma unroll
                for (int r = 0; r < 4; r++) acc[m][t][j][r] = 0.f;

    const int ld_row = tid >> 2, ld_seg = tid & 3;
    const int a_row  = (m0 + ld_row < cnt) ? (m0 + ld_row) : (cnt - 1);
    const __half* a_src = g_embc + (size_t)a_row * E_ + ld_seg * 8;
    const size_t  b_off = (size_t)(n0 + ld_row) * E_ + ld_seg * 8;
    auto load_stage = [&](int kt, int s) {
        const uint32_t base = sb + s * STAGE_BYTES;
        const int k0 = kt * BK;
        cp16(base + ld_row * (SROW * 2) + ld_seg * 16, a_src + k0);
        uint32_t d = base + A_TILE + ld_row * (SROW * 2) + ld_seg * 16;
        #pragma unroll
        for (int t = 0; t < 3; t++)
            cp16(d + t * B_TILE, g_wt[t] + b_off + k0);
        CP_COMMIT();
    };

    const int lq = lane >> 3, lr = lane & 7;

    load_stage(0, 0);
    load_stage(1, 1);

    for (int kt = 0; kt < NKT; ++kt) {
        if (kt < NKT - 1) { CP_WAIT(1); } else { CP_WAIT(0); }
        __syncthreads();

        const uint32_t base = sb + (kt % STAGES) * STAGE_BYTES;
        #pragma unroll
        for (int ks = 0; ks < 2; ++ks) {
            uint32_t aF[2][4];
            #pragma unroll
            for (int t = 0; t < 2; t++) {
                int row = wm * 32 + t * 16 + (lq & 1) * 8 + lr;
                ldsm4(aF[t], base + row * (SROW * 2) + ks * 32 + (lq >> 1) * 16);
            }
            #pragma unroll
            for (int mat = 0; mat < 3; mat++) {
                uint32_t bF[4];
                {
                    int row = wn * 16 + (lq >> 1) * 8 + lr;
                    ldsm4(bF, base + A_TILE + mat * B_TILE
                             + row * (SROW * 2) + ks * 32 + (lq & 1) * 16);
                }
                #pragma unroll
                for (int t = 0; t < 2; t++)
                    #pragma unroll
                    for (int j = 0; j < 2; j++)
                        mma16816(acc[mat][t][j], aF[t], &bF[j * 2]);
            }
        }
        // trailing load (measured best position): writes stage (kt+2)%3 ==
        // (kt-1)%3 whose readers all completed before this iteration's barrier.
        if (kt + 2 < NKT) load_stage(kt + 2, (kt + 2) % STAGES);
    }

    // ---- epilogue: gate math (2 EX2 + 1 RCP per element), half2 stores -----
    #pragma unroll
    for (int j = 0; j < 2; j++) {
        int col = n0 + wn * 16 + j * 8 + (lane & 3) * 2;
        float2 bfv = *(const float2*)(bfb + col);
        float2 biv = *(const float2*)(bib + col);
        float2 bhv = *(const float2*)(bhb + col);
        #pragma unroll
        for (int t = 0; t < 2; t++) {
            #pragma unroll
            for (int rh = 0; rh < 2; rh++) {
                int row = m0 + wm * 32 + t * 16 + (lane >> 2) + rh * 8;
                if (row >= cnt) continue;
                float ef0 = __expf(-(acc[0][t][j][rh * 2 + 0] + bfv.x));
                float ef1 = __expf(-(acc[0][t][j][rh * 2 + 1] + bfv.y));
                float ei0 = __expf(-(acc[1][t][j][rh * 2 + 0] + biv.x));
                float ei1 = __expf(-(acc[1][t][j][rh * 2 + 1] + biv.y));
                float zh0 = acc[2][t][j][rh * 2 + 0] + bhv.x;
                float zh1 = acc[2][t][j][rh * 2 + 1] + bhv.y;
                float r0 = 1.f / (2.f + ef0 + ei0);
                float r1 = 1.f / (2.f + ef1 + ei1);
                __half2 p0 = __floats2half2_rn((1.f + ei0) * r0, (1.f + ef0) * r0 * zh0);
                __half2 p1 = __floats2half2_rn((1.f + ei1) * r1, (1.f + ef1) * r1 * zh1);
                *(uint2*)&g_tab[(size_t)row * U_ + col] =
                    make_uint2(*(uint32_t*)&p0, *(uint32_t*)&p1);
            }
        }
    }
}

// ---------------- kernel 2a: chunked scan, 4 u per thread (uint4 loads) -----
__global__ __launch_bounds__(256) void scan_part()
{
    const int u0 = threadIdx.x * 4;
    const int b = blockIdx.y;
    const int c = blockIdx.z;
    const int4* sr4 = (const int4*)(g_sent + b * S_ + c * CHL);

    float P0 = 1.f, P1 = 1.f, P2 = 1.f, P3 = 1.f;
    float h0 = 0.f, h1 = 0.f, h2 = 0.f, h3 = 0.f;
    #pragma unroll 2
    for (int tq = 0; tq < CHL / 4; tq++) {
        int4 rid4 = __ldg(&sr4[tq]);
        int rids[4] = { rid4.x, rid4.y, rid4.z, rid4.w };
        #pragma unroll
        for (int s = 0; s < 4; s++) {
            uint4 v = __ldg((const uint4*)(g_tab + (size_t)rids[s] * U_ + u0));
            float2 a0 = __half22float2(*(__half2*)&v.x);
            float2 a1 = __half22float2(*(__half2*)&v.y);
            float2 a2 = __half22float2(*(__half2*)&v.z);
            float2 a3 = __half22float2(*(__half2*)&v.w);
            h0 = fmaf(a0.x, h0, a0.y);  P0 *= a0.x;
            h1 = fmaf(a1.x, h1, a1.y);  P1 *= a1.x;
            h2 = fmaf(a2.x, h2, a2.y);  P2 *= a2.x;
            h3 = fmaf(a3.x, h3, a3.y);  P3 *= a3.x;
        }
    }
    size_t idx = ((size_t)c * B_ + b) * U_ + u0;
    *(float4*)&g_P[idx] = make_float4(P0, P1, P2, P3);
    *(float4*)&g_Q[idx] = make_float4(h0, h1, h2, h3);
}

// ---------------- kernel 3: fused combine + head -----------------------------
__global__ __launch_bounds__(256) void head_kernel(
    const float* __restrict__ W1, const float* __restrict__ b1,
    const float* __restrict__ W2, const float* __restrict__ b2,
    float* __restrict__ out)
{
    __shared__ float w12[U_];
    __shared__ float red[256];
    const int b = blockIdx.x, tid = threadIdx.x;

    for (int u = tid; u < U_; u += 256) {
        float s = 0.f;
        #pragma unroll
        for (int c = 0; c < 64; c++) s = fmaf(W1[u * 64 + c], W2[c], s);
        w12[u] = s;
    }

    float p = 0.f;
    #pragma unroll
    for (int q = 0; q < U_ / 256; q++) {
        int u = q * 256 + tid;
        float h = 0.f;
        #pragma unroll
        for (int c = 0; c < NCH; c++) {
            size_t idx = ((size_t)c * B_ + b) * U_ + u;
            h = fmaf(g_P[idx], h, g_Q[idx]);
        }
        p = fmaf(h, w12[u], p);
    }
    __syncthreads();
    red[tid] = p;
    __syncthreads();
    #pragma unroll
    for (int s = 128; s > 0; s >>= 1) {
        if (tid < s) red[tid] += red[tid + s];
        __syncthreads();
    }
    if (tid == 0) {
        float c = 0.f;
        #pragma unroll
        for (int j = 0; j < 64; j++) c = fmaf(b1[j], W2[j], c);
        out[b] = 1.f / (1.f + expf(-(red[0] + c + b2[0])));
    }
}

// ---------------- host -------------------------------------------------------
extern "C" void kernel_launch(void* const* d_in, const int* in_sizes, int n_in,
                              void* d_out, int out_size)
{
    const int*   sent = (const int*)  d_in[0];
    const float* emb  = (const float*)d_in[1];
    const float* Wf   = (const float*)d_in[2];
    const float* bf   = (const float*)d_in[3];
    const float* Wi   = (const float*)d_in[4];
    const float* bi   = (const float*)d_in[5];
    const float* Wh   = (const float*)d_in[6];
    const float* bh   = (const float*)d_in[7];
    const float* W1   = (const float*)d_in[8];
    const float* b1   = (const float*)d_in[9];
    const float* W2   = (const float*)d_in[10];
    const float* b2   = (const float*)d_in[11];
    float* out = (float*)d_out;

    cudaFuncSetAttribute(gates_mma, cudaFuncAttributeMaxDynamicSharedMemorySize, SMEM_DYN);

    zero_k<<<(V_ + 255) / 256, 256>>>();
    mark_k<<<(B_ * S_) / 256, 256>>>(sent);
    sentmap_k<<<(B_ * S_) / 256, 256>>>(sent);
    gather_emb_k<<<(V_ + 7) / 8, 256>>>(emb);
    transpose_w_k<<<dim3(U_ / 32, E_ / 32, 3), dim3(32, 8)>>>(Wf, Wi, Wh);
    gates_mma<<<dim3(U_ / BN, (V_ + BM - 1) / BM), 256, SMEM_DYN>>>(bf, bi, bh);
    scan_part<<<dim3(1, B_, NCH), 256>>>();
    head_kernel<<<B_, 256>>>(W1, b1, W2, b2, out);
}